// round 1
// baseline (speedup 1.0000x reference)
#include <cuda_runtime.h>
#include <cuda_bf16.h>
#include <math.h>

// Problem constants
#define B_  16
#define CDIM 128          // D_MODEL = D_INNER = 128
#define Hh  96
#define Ww  96
#define LSEQ (Hh*Ww)      // 9216
#define DSTATE 2
#define DTRANK 8
#define DCONV 4
#define OUTC 128
#define NPROJ 12          // DTRANK + 2*DSTATE
#define CHUNK 96
#define NCHUNK (LSEQ/CHUNK)   // 96

// ---------------- device scratch (no runtime allocation allowed) ------------
__device__ float g_xraw[(size_t)B_*LSEQ*CDIM];   // pre-conv x_in  (75.5 MB)
__device__ float g_zsilu[(size_t)B_*LSEQ*CDIM];  // silu(z)        (75.5 MB)
__device__ float g_aggA[(size_t)B_*NCHUNK*CDIM*DSTATE];
__device__ float g_aggH[(size_t)B_*NCHUNK*CDIM*DSTATE];
__device__ float g_hinit[(size_t)B_*NCHUNK*CDIM*DSTATE];

__device__ __forceinline__ float silu_f(float v) {
    return v / (1.0f + expf(-v));
}
__device__ __forceinline__ float softplus_f(float v) {
    return (v > 20.0f) ? v : log1pf(expf(v));
}

// ---------------------------------------------------------------------------
// K1: in_proj GEMM.  tokens[b,l,c] = x[b,c,l]  (x is (B,C,H*W))
// out e<128 -> g_xraw[b,l,e];  e>=128 -> g_zsilu[b,l,e-128] = silu(val)
// Tiling: BM=64 (l), BN=64 (e), BK=16, 256 threads, 4x4 microtile.
// ---------------------------------------------------------------------------
__global__ __launch_bounds__(256)
void k_inproj(const float* __restrict__ x, const float* __restrict__ Wi) {
    __shared__ float As[16][64];
    __shared__ float Bs[16][64];

    const int b  = blockIdx.z;
    const int m0 = blockIdx.x * 64;   // token tile
    const int n0 = blockIdx.y * 64;   // output tile
    const float* xb = x + (size_t)b * CDIM * LSEQ;

    const int tid = threadIdx.x;
    const int tx = tid & 15;          // 0..15 -> n microtile
    const int ty = tid >> 4;          // 0..15 -> m microtile

    const int lm  = tid & 63;         // A loader: m
    const int lkb = tid >> 6;         // A loader: k base (0..3)
    const int wk  = tid & 15;         // B loader: k
    const int wn0 = tid >> 4;         // B loader: n base (0..15)

    float acc[4][4];
#pragma unroll
    for (int i = 0; i < 4; i++)
#pragma unroll
        for (int j = 0; j < 4; j++) acc[i][j] = 0.f;

    for (int k0 = 0; k0 < CDIM; k0 += 16) {
#pragma unroll
        for (int i = 0; i < 4; i++)
            As[lkb + i*4][lm] = xb[(size_t)(k0 + lkb + i*4) * LSEQ + m0 + lm];
#pragma unroll
        for (int i = 0; i < 4; i++)
            Bs[wk][wn0 + i*16] = Wi[(size_t)(n0 + wn0 + i*16) * CDIM + k0 + wk];
        __syncthreads();

#pragma unroll
        for (int k = 0; k < 16; k++) {
            float4 fa = *reinterpret_cast<const float4*>(&As[k][ty*4]);
            float4 fb = *reinterpret_cast<const float4*>(&Bs[k][tx*4]);
            float fav[4] = {fa.x, fa.y, fa.z, fa.w};
            float fbv[4] = {fb.x, fb.y, fb.z, fb.w};
#pragma unroll
            for (int i = 0; i < 4; i++)
#pragma unroll
                for (int j = 0; j < 4; j++)
                    acc[i][j] = fmaf(fav[i], fbv[j], acc[i][j]);
        }
        __syncthreads();
    }

    // epilogue: 4 consecutive e per thread -> float4 stores
#pragma unroll
    for (int i = 0; i < 4; i++) {
        const int l = m0 + ty*4 + i;
        const size_t rowbase = ((size_t)b * LSEQ + l) * CDIM;
        const int e = n0 + tx*4;
        if (e < CDIM) {
            float4 v = make_float4(acc[i][0], acc[i][1], acc[i][2], acc[i][3]);
            *reinterpret_cast<float4*>(&g_xraw[rowbase + e]) = v;
        } else {
            float4 v = make_float4(silu_f(acc[i][0]), silu_f(acc[i][1]),
                                   silu_f(acc[i][2]), silu_f(acc[i][3]));
            *reinterpret_cast<float4*>(&g_zsilu[rowbase + e - CDIM]) = v;
        }
    }
}

// ---------------------------------------------------------------------------
// K2: Phase A — per chunk: conv+silu, x_proj, dt_proj, dA, local scan.
// Outputs per (b,chunk,d,s): prod(dA), local h_end.  128 threads (thread=d).
// dyn smem: xi[96*129] + xw[12*129] + xdbl[96*12]
// ---------------------------------------------------------------------------
#define SM_A_FLOATS (96*129 + 12*129 + 96*12)

__global__ __launch_bounds__(128)
void k_phaseA(const float* __restrict__ conv_w, const float* __restrict__ conv_b,
              const float* __restrict__ x_proj_w, const float* __restrict__ dt_proj_w,
              const float* __restrict__ dt_proj_b, const float* __restrict__ A_log) {
    extern __shared__ float sm[];
    float* xi_s   = sm;                    // [96][129]
    float* xw_s   = xi_s + 96*129;         // [12][129]
    float* xdbl_s = xw_s + 12*129;         // [96][12]

    const int ch = blockIdx.x;
    const int b  = blockIdx.y;
    const int l0 = ch * CHUNK;
    const int d  = threadIdx.x;

    for (int i = d; i < NPROJ*CDIM; i += 128) {
        int j = i >> 7, k = i & 127;
        xw_s[j*129 + k] = x_proj_w[i];
    }

    const float cw0 = conv_w[d*4+0], cw1 = conv_w[d*4+1];
    const float cw2 = conv_w[d*4+2], cw3 = conv_w[d*4+3];
    const float cb  = conv_b[d];
    const float* xr = g_xraw + (size_t)b * LSEQ * CDIM;

    float p0 = (l0 >= 3) ? xr[(size_t)(l0-3)*CDIM + d] : 0.f;
    float p1 = (l0 >= 2) ? xr[(size_t)(l0-2)*CDIM + d] : 0.f;
    float p2 = (l0 >= 1) ? xr[(size_t)(l0-1)*CDIM + d] : 0.f;

    for (int l = 0; l < CHUNK; l++) {
        float c = xr[(size_t)(l0+l)*CDIM + d];
        float a = fmaf(cw0,p0, fmaf(cw1,p1, fmaf(cw2,p2, fmaf(cw3,c, cb))));
        xi_s[l*129 + d] = silu_f(a);
        p0 = p1; p1 = p2; p2 = c;
    }
    __syncthreads();

    // x_dbl: 96 tokens x 12 projections, K=128
    for (int p = d; p < CHUNK*NPROJ; p += 128) {
        int l = p / NPROJ, j = p % NPROJ;
        const float* xrow = &xi_s[l*129];
        const float* wrow = &xw_s[j*129];
        float s = 0.f;
#pragma unroll 8
        for (int k = 0; k < CDIM; k++) s = fmaf(xrow[k], wrow[k], s);
        xdbl_s[l*NPROJ + j] = s;
    }
    __syncthreads();

    float wdt[DTRANK];
#pragma unroll
    for (int r = 0; r < DTRANK; r++) wdt[r] = dt_proj_w[d*DTRANK + r];
    const float bdt = dt_proj_b[d];
    const float a0 = -expf(A_log[d*2+0]);
    const float a1 = -expf(A_log[d*2+1]);

    float h0 = 0.f, h1 = 0.f, pr0 = 1.f, pr1 = 1.f;
    for (int l = 0; l < CHUNK; l++) {
        const float* xd = &xdbl_s[l*NPROJ];
        float t = bdt;
#pragma unroll
        for (int r = 0; r < DTRANK; r++) t = fmaf(xd[r], wdt[r], t);
        float dt = softplus_f(t);
        float xi = xi_s[l*129 + d];
        float e0 = expf(dt*a0), e1 = expf(dt*a1);
        float dbx = dt * xi;
        h0 = fmaf(e0, h0, dbx * xd[8]);
        h1 = fmaf(e1, h1, dbx * xd[9]);
        pr0 *= e0; pr1 *= e1;
    }
    const size_t base = (((size_t)b*NCHUNK + ch)*CDIM + d)*DSTATE;
    g_aggA[base+0] = pr0; g_aggA[base+1] = pr1;
    g_aggH[base+0] = h0;  g_aggH[base+1] = h1;
}

// ---------------------------------------------------------------------------
// K3: chain chunk aggregates -> entry state per chunk. 4096 chains, len 96.
// ---------------------------------------------------------------------------
__global__ __launch_bounds__(256)
void k_combine() {
    const int g = blockIdx.x * blockDim.x + threadIdx.x;   // 0..4095
    const int b = g >> 8;
    const int rem = g & 255;                               // d*2+s
    float h = 0.f;
    for (int ch = 0; ch < NCHUNK; ch++) {
        const size_t idx = (((size_t)b*NCHUNK + ch) * CDIM * DSTATE) + rem;
        g_hinit[idx] = h;
        h = fmaf(g_aggA[idx], h, g_aggH[idx]);
    }
}

// ---------------------------------------------------------------------------
// K4: Phase C — recompute conv/x_proj/dt, scan with correct entry state,
// gate with silu(z), out_proj GEMM (96x128 @ 128x128) + LayerNorm + write.
// 256 threads.
// dyn smem: y[96*129] + xw[12*129] + xdbl[96*12] + Ws[16*128] + outs[128*33]
//           + mu[32] + rs[32]
// ---------------------------------------------------------------------------
#define SM_C_FLOATS (96*129 + 12*129 + 96*12 + 16*128 + 128*33 + 64)

__global__ __launch_bounds__(256)
void k_phaseC(const float* __restrict__ conv_w, const float* __restrict__ conv_b,
              const float* __restrict__ x_proj_w, const float* __restrict__ dt_proj_w,
              const float* __restrict__ dt_proj_b, const float* __restrict__ A_log,
              const float* __restrict__ D_param, const float* __restrict__ Wout,
              const float* __restrict__ gamma, const float* __restrict__ beta,
              float* __restrict__ out) {
    extern __shared__ float sm[];
    float* y_s    = sm;                       // [96][129]  xi -> y in place
    float* xw_s   = y_s + 96*129;             // [12][129]
    float* xdbl_s = xw_s + 12*129;            // [96][12]
    float* Ws     = xdbl_s + 96*12;           // [16][128]
    float* out_s  = Ws + 16*128;              // [128][33]
    float* mu_s   = out_s + 128*33;           // [32]
    float* rs_s   = mu_s + 32;                // [32]

    const int ch = blockIdx.x;
    const int b  = blockIdx.y;
    const int l0 = ch * CHUNK;
    const int tid = threadIdx.x;
    const int d    = tid & 127;
    const int half = tid >> 7;

    for (int i = tid; i < NPROJ*CDIM; i += 256) {
        int j = i >> 7, k = i & 127;
        xw_s[j*129 + k] = x_proj_w[i];
    }

    // conv + silu: two halves of 48 tokens, threads 0..127 and 128..255
    {
        const float cw0 = conv_w[d*4+0], cw1 = conv_w[d*4+1];
        const float cw2 = conv_w[d*4+2], cw3 = conv_w[d*4+3];
        const float cb  = conv_b[d];
        const float* xr = g_xraw + (size_t)b * LSEQ * CDIM;
        const int ls = half * 48;
        const int la0 = l0 + ls;
        float p0 = (la0 >= 3) ? xr[(size_t)(la0-3)*CDIM + d] : 0.f;
        float p1 = (la0 >= 2) ? xr[(size_t)(la0-2)*CDIM + d] : 0.f;
        float p2 = (la0 >= 1) ? xr[(size_t)(la0-1)*CDIM + d] : 0.f;
        for (int l = ls; l < ls + 48; l++) {
            float c = xr[(size_t)(l0+l)*CDIM + d];
            float a = fmaf(cw0,p0, fmaf(cw1,p1, fmaf(cw2,p2, fmaf(cw3,c, cb))));
            y_s[l*129 + d] = silu_f(a);
            p0 = p1; p1 = p2; p2 = c;
        }
    }
    __syncthreads();

    for (int p = tid; p < CHUNK*NPROJ; p += 256) {
        int l = p / NPROJ, j = p % NPROJ;
        const float* xrow = &y_s[l*129];
        const float* wrow = &xw_s[j*129];
        float s = 0.f;
#pragma unroll 8
        for (int k = 0; k < CDIM; k++) s = fmaf(xrow[k], wrow[k], s);
        xdbl_s[l*NPROJ + j] = s;
    }
    __syncthreads();

    // scan + gate (threads 0..127 only; writes y into y_s in place)
    if (tid < 128) {
        float wdt[DTRANK];
#pragma unroll
        for (int r = 0; r < DTRANK; r++) wdt[r] = dt_proj_w[d*DTRANK + r];
        const float bdt = dt_proj_b[d];
        const float a0 = -expf(A_log[d*2+0]);
        const float a1 = -expf(A_log[d*2+1]);
        const float Dp = D_param[d];
        const size_t hbase = (((size_t)b*NCHUNK + ch)*CDIM + d)*DSTATE;
        float h0 = g_hinit[hbase+0];
        float h1 = g_hinit[hbase+1];
        const float* zs = g_zsilu + ((size_t)b*LSEQ + l0) * CDIM;

        for (int l = 0; l < CHUNK; l++) {
            const float* xd = &xdbl_s[l*NPROJ];
            float t = bdt;
#pragma unroll
            for (int r = 0; r < DTRANK; r++) t = fmaf(xd[r], wdt[r], t);
            float dt = softplus_f(t);
            float xi = y_s[l*129 + d];
            float e0 = expf(dt*a0), e1 = expf(dt*a1);
            float dbx = dt * xi;
            h0 = fmaf(e0, h0, dbx * xd[8]);
            h1 = fmaf(e1, h1, dbx * xd[9]);
            float yv = fmaf(h0, xd[10], fmaf(h1, xd[11], Dp * xi));
            float zv = zs[(size_t)l*CDIM + d];
            y_s[l*129 + d] = yv * zv;
        }
    }
    __syncthreads();

    // out_proj GEMM + LN, 3 passes of 32 tokens
    const int tx = tid & 31;      // output microtile: o = tx*4+j
    const int ty = tid >> 5;      // token microtile:  l = ty*4+i (within pass)
    const int lane = tid & 31;
    const int wid  = tid >> 5;

    for (int pass = 0; pass < 3; pass++) {
        float acc[4][4];
#pragma unroll
        for (int i = 0; i < 4; i++)
#pragma unroll
            for (int j = 0; j < 4; j++) acc[i][j] = 0.f;

        for (int k0 = 0; k0 < CDIM; k0 += 16) {
            __syncthreads();                 // protect Ws / out_s reuse
            for (int i2 = tid; i2 < 16*128; i2 += 256) {
                int kk = i2 & 15, o = i2 >> 4;
                Ws[kk*128 + o] = Wout[(size_t)o*CDIM + k0 + kk];
            }
            __syncthreads();
#pragma unroll
            for (int kk = 0; kk < 16; kk++) {
                float4 fb = reinterpret_cast<const float4*>(&Ws[kk*128])[tx];
                float fbv[4] = {fb.x, fb.y, fb.z, fb.w};
                float fav[4];
#pragma unroll
                for (int i = 0; i < 4; i++)
                    fav[i] = y_s[(pass*32 + ty*4 + i)*129 + k0 + kk];
#pragma unroll
                for (int i = 0; i < 4; i++)
#pragma unroll
                    for (int j = 0; j < 4; j++)
                        acc[i][j] = fmaf(fav[i], fbv[j], acc[i][j]);
            }
        }
        __syncthreads();
#pragma unroll
        for (int i = 0; i < 4; i++)
#pragma unroll
            for (int j = 0; j < 4; j++)
                out_s[(tx*4 + j)*33 + (ty*4 + i)] = acc[i][j];
        __syncthreads();

        // LayerNorm stats: 32 tokens, one warp per 4 tokens
        for (int t = wid; t < 32; t += 8) {
            float v0 = out_s[(lane     )*33 + t];
            float v1 = out_s[(lane + 32)*33 + t];
            float v2 = out_s[(lane + 64)*33 + t];
            float v3 = out_s[(lane + 96)*33 + t];
            float s = v0+v1+v2+v3;
            float q = v0*v0 + v1*v1 + v2*v2 + v3*v3;
#pragma unroll
            for (int off = 16; off > 0; off >>= 1) {
                s += __shfl_xor_sync(0xffffffffu, s, off);
                q += __shfl_xor_sync(0xffffffffu, q, off);
            }
            if (lane == 0) {
                float mu = s * (1.0f/128.0f);
                float var = q * (1.0f/128.0f) - mu*mu;
                mu_s[t] = mu;
                rs_s[t] = rsqrtf(var + 1e-5f);
            }
        }
        __syncthreads();

        // normalized, transposed, coalesced writes: out[b, o, l0+pass*32+l]
        for (int p = tid; p < 32*128; p += 256) {
            int l = p & 31, o = p >> 5;
            float v = (out_s[o*33 + l] - mu_s[l]) * rs_s[l] * gamma[o] + beta[o];
            out[((size_t)(b*OUTC + o))*LSEQ + l0 + pass*32 + l] = v;
        }
    }
}

// ---------------------------------------------------------------------------
extern "C" void kernel_launch(void* const* d_in, const int* in_sizes, int n_in,
                              void* d_out, int out_size) {
    const float* x          = (const float*)d_in[0];
    const float* in_proj_w  = (const float*)d_in[1];
    const float* conv_w     = (const float*)d_in[2];
    const float* conv_b     = (const float*)d_in[3];
    const float* x_proj_w   = (const float*)d_in[4];
    const float* dt_proj_w  = (const float*)d_in[5];
    const float* dt_proj_b  = (const float*)d_in[6];
    const float* A_log      = (const float*)d_in[7];
    const float* D_param    = (const float*)d_in[8];
    const float* out_proj_w = (const float*)d_in[9];
    const float* ln_gamma   = (const float*)d_in[10];
    const float* ln_beta    = (const float*)d_in[11];
    float* out = (float*)d_out;

    const int smA = SM_A_FLOATS * sizeof(float);   // ~60.3 KB
    const int smC = SM_C_FLOATS * sizeof(float);   // ~85.7 KB
    cudaFuncSetAttribute(k_phaseA, cudaFuncAttributeMaxDynamicSharedMemorySize, smA);
    cudaFuncSetAttribute(k_phaseC, cudaFuncAttributeMaxDynamicSharedMemorySize, smC);

    k_inproj<<<dim3(LSEQ/64, 4, B_), 256>>>(x, in_proj_w);
    k_phaseA<<<dim3(NCHUNK, B_), 128, smA>>>(conv_w, conv_b, x_proj_w,
                                             dt_proj_w, dt_proj_b, A_log);
    k_combine<<<16, 256>>>();
    k_phaseC<<<dim3(NCHUNK, B_), 256, smC>>>(conv_w, conv_b, x_proj_w,
                                             dt_proj_w, dt_proj_b, A_log,
                                             D_param, out_proj_w, ln_gamma, ln_beta,
                                             out);
}

// round 2
// speedup vs baseline: 1.8593x; 1.8593x over previous
#include <cuda_runtime.h>
#include <math.h>

#define B_    16
#define CDIM  128
#define LSEQ  9216
#define DSTATE 2
#define DTRANK 8
#define OUTC  128
#define NPROJ 12
#define CHUNK 96
#define NCHUNK 96
#define LOG2E 1.4426950408889634f

// ---------------- device scratch ----------------
__device__ float g_xraw [(size_t)B_*LSEQ*CDIM];
__device__ float g_zsilu[(size_t)B_*LSEQ*CDIM];
__device__ float g_xi   [(size_t)B_*LSEQ*CDIM];
__device__ float g_dt   [(size_t)B_*LSEQ*CDIM];
__device__ float g_y    [(size_t)B_*LSEQ*CDIM];
__device__ float g_bc   [(size_t)B_*LSEQ*4];     // B0,B1,C0,C1 per token
__device__ float g_aggA [(size_t)B_*NCHUNK*CDIM*DSTATE];
__device__ float g_aggH [(size_t)B_*NCHUNK*CDIM*DSTATE];
__device__ float g_hinit[(size_t)B_*NCHUNK*CDIM*DSTATE];

__device__ __forceinline__ float silu_f(float v) {
    return __fdividef(v, 1.0f + __expf(-v));
}

// ---------------------------------------------------------------------------
// K1: in_proj SGEMM.  A[m=(b,l)][k=c] = x[b][c][l],  B = in_proj_w[256][128].
// BM=128, BN=128, BK=16, 256 threads, 8x8 microtile.
// n0==0   -> g_xraw[b][l][e]
// n0==128 -> g_zsilu[b][l][e-128] = silu(val)
// ---------------------------------------------------------------------------
__global__ __launch_bounds__(256, 2)
void k_inproj(const float* __restrict__ x, const float* __restrict__ Wi) {
    __shared__ float As[16*132];
    __shared__ float Bs[16*132];
    const int b  = blockIdx.z;
    const int m0 = blockIdx.x * 128;
    const int n0 = blockIdx.y * 128;
    const float* xb = x + (size_t)b * CDIM * LSEQ;
    const int tid = threadIdx.x;
    const int tx = tid & 15, ty = tid >> 4;

    float acc[8][8];
#pragma unroll
    for (int i = 0; i < 8; i++)
#pragma unroll
        for (int j = 0; j < 8; j++) acc[i][j] = 0.f;

    const int ak  = tid >> 5;          // 0..7
    const int am4 = (tid & 31) * 4;
    const int lrow = tid >> 2;         // 0..63
    const int lc   = tid & 3;

    for (int k0 = 0; k0 < CDIM; k0 += 16) {
        // A: coalesced float4 along l
#pragma unroll
        for (int r = 0; r < 2; r++) {
            int kk = ak + r*8;
            float4 v = *reinterpret_cast<const float4*>(
                &xb[(size_t)(k0 + kk)*LSEQ + m0 + am4]);
            *reinterpret_cast<float4*>(&As[kk*132 + am4]) = v;
        }
        // B: float4 along k, scatter-transpose into Bs[k][n]
#pragma unroll
        for (int r = 0; r < 2; r++) {
            int n = lrow + r*64;
            float4 w = *reinterpret_cast<const float4*>(
                &Wi[(size_t)(n0 + n)*CDIM + k0 + lc*4]);
            Bs[(lc*4+0)*132 + n] = w.x;
            Bs[(lc*4+1)*132 + n] = w.y;
            Bs[(lc*4+2)*132 + n] = w.z;
            Bs[(lc*4+3)*132 + n] = w.w;
        }
        __syncthreads();
#pragma unroll
        for (int k = 0; k < 16; k++) {
            float a[8], bv[8];
            *reinterpret_cast<float4*>(&a[0]) = *reinterpret_cast<const float4*>(&As[k*132 + ty*8]);
            *reinterpret_cast<float4*>(&a[4]) = *reinterpret_cast<const float4*>(&As[k*132 + ty*8 + 4]);
            *reinterpret_cast<float4*>(&bv[0]) = *reinterpret_cast<const float4*>(&Bs[k*132 + tx*8]);
            *reinterpret_cast<float4*>(&bv[4]) = *reinterpret_cast<const float4*>(&Bs[k*132 + tx*8 + 4]);
#pragma unroll
            for (int i = 0; i < 8; i++)
#pragma unroll
                for (int j = 0; j < 8; j++)
                    acc[i][j] = fmaf(a[i], bv[j], acc[i][j]);
        }
        __syncthreads();
    }

#pragma unroll
    for (int i = 0; i < 8; i++) {
        const int l = m0 + ty*8 + i;
        const size_t rowbase = ((size_t)b * LSEQ + l) * CDIM;
        const int e = tx*8;   // 0..120 within this half
        if (n0 == 0) {
            float4 v0 = make_float4(acc[i][0], acc[i][1], acc[i][2], acc[i][3]);
            float4 v1 = make_float4(acc[i][4], acc[i][5], acc[i][6], acc[i][7]);
            *reinterpret_cast<float4*>(&g_xraw[rowbase + e])     = v0;
            *reinterpret_cast<float4*>(&g_xraw[rowbase + e + 4]) = v1;
        } else {
            float4 v0 = make_float4(silu_f(acc[i][0]), silu_f(acc[i][1]),
                                    silu_f(acc[i][2]), silu_f(acc[i][3]));
            float4 v1 = make_float4(silu_f(acc[i][4]), silu_f(acc[i][5]),
                                    silu_f(acc[i][6]), silu_f(acc[i][7]));
            *reinterpret_cast<float4*>(&g_zsilu[rowbase + e])     = v0;
            *reinterpret_cast<float4*>(&g_zsilu[rowbase + e + 4]) = v1;
        }
    }
}

// ---------------------------------------------------------------------------
// K2: phaseA — conv+silu -> xi (smem + gmem), x_dbl GEMM -> B/C coeffs (gmem),
// dt (gmem), chunk aggregates (prod dA via exp(a*sum dt), local h).
// 128 threads (thread = d).
// ---------------------------------------------------------------------------
#define SM2_FLOATS (96*132 + 12*132 + 96*16)

__global__ __launch_bounds__(128)
void k_phaseA(const float* __restrict__ conv_w, const float* __restrict__ conv_b,
              const float* __restrict__ x_proj_w, const float* __restrict__ dt_proj_w,
              const float* __restrict__ dt_proj_b, const float* __restrict__ A_log) {
    extern __shared__ float sm[];
    float* xi_s = sm;                 // [96][132]
    float* xw_s = sm + 96*132;        // [12][132]
    float* xd_s = xw_s + 12*132;      // [96][16]

    const int ch = blockIdx.x;
    const int b  = blockIdx.y;
    const int l0 = ch * CHUNK;
    const int d  = threadIdx.x;

    for (int i = d; i < NPROJ*CDIM; i += 128)
        xw_s[(i >> 7)*132 + (i & 127)] = x_proj_w[i];

    // conv + silu
    {
        const float cw0 = conv_w[d*4+0], cw1 = conv_w[d*4+1];
        const float cw2 = conv_w[d*4+2], cw3 = conv_w[d*4+3];
        const float cb  = conv_b[d];
        const float* xr = g_xraw + (size_t)b * LSEQ * CDIM;
        float* xo = g_xi + ((size_t)b * LSEQ + l0) * CDIM + d;
        float p0 = (l0 >= 3) ? xr[(size_t)(l0-3)*CDIM + d] : 0.f;
        float p1 = (l0 >= 2) ? xr[(size_t)(l0-2)*CDIM + d] : 0.f;
        float p2 = (l0 >= 1) ? xr[(size_t)(l0-1)*CDIM + d] : 0.f;
#pragma unroll 4
        for (int l = 0; l < CHUNK; l++) {
            float c = xr[(size_t)(l0+l)*CDIM + d];
            float a = fmaf(cw0,p0, fmaf(cw1,p1, fmaf(cw2,p2, fmaf(cw3,c, cb))));
            float v = silu_f(a);
            xi_s[l*132 + d] = v;
            xo[(size_t)l*CDIM] = v;
            p0 = p1; p1 = p2; p2 = c;
        }
    }
    __syncthreads();

    // x_dbl: 96 x 12 dots of K=128 (float4)
    {
        float* bco = g_bc + ((size_t)b * LSEQ + l0) * 4;
        for (int p = d; p < CHUNK*NPROJ; p += 128) {
            int l = p / 12, j = p - l*12;
            const float4* xr4 = reinterpret_cast<const float4*>(&xi_s[l*132]);
            const float4* wr4 = reinterpret_cast<const float4*>(&xw_s[j*132]);
            float s = 0.f;
#pragma unroll
            for (int k = 0; k < 32; k++) {
                float4 xa = xr4[k], wa = wr4[k];
                s = fmaf(xa.x, wa.x, s); s = fmaf(xa.y, wa.y, s);
                s = fmaf(xa.z, wa.z, s); s = fmaf(xa.w, wa.w, s);
            }
            xd_s[l*16 + j] = s;
            if (j >= 8) bco[l*4 + (j-8)] = s;
        }
    }
    __syncthreads();

    // dt + aggregates
    {
        float wdt[DTRANK];
#pragma unroll
        for (int r = 0; r < DTRANK; r++) wdt[r] = dt_proj_w[d*DTRANK + r];
        const float bdt = dt_proj_b[d];
        const float a0L = -__expf(A_log[2*d+0]) * LOG2E;
        const float a1L = -__expf(A_log[2*d+1]) * LOG2E;
        float* dto = g_dt + ((size_t)b * LSEQ + l0) * CDIM + d;

        float h0 = 0.f, h1 = 0.f, sdt = 0.f;
#pragma unroll 2
        for (int l = 0; l < CHUNK; l++) {
            const float* xd = &xd_s[l*16];
            float t = bdt;
#pragma unroll
            for (int r = 0; r < DTRANK; r++) t = fmaf(xd[r], wdt[r], t);
            float ex = __expf(t);
            float dt = (t > 20.f) ? t : __logf(1.f + ex);
            dto[(size_t)l*CDIM] = dt;
            sdt += dt;
            float e0 = exp2f(dt * a0L);
            float e1 = exp2f(dt * a1L);
            float dbx = dt * xi_s[l*132 + d];
            h0 = fmaf(e0, h0, dbx * xd[8]);
            h1 = fmaf(e1, h1, dbx * xd[9]);
        }
        const size_t base = (((size_t)b*NCHUNK + ch)*CDIM + d)*DSTATE;
        g_aggA[base+0] = exp2f(a0L * sdt);
        g_aggA[base+1] = exp2f(a1L * sdt);
        g_aggH[base+0] = h0;
        g_aggH[base+1] = h1;
    }
}

// ---------------------------------------------------------------------------
// K3: chain chunk aggregates -> entry state per chunk (4096 chains, len 96).
// ---------------------------------------------------------------------------
__global__ __launch_bounds__(256)
void k_combine() {
    const int g = blockIdx.x * blockDim.x + threadIdx.x;   // 0..4095
    const int b = g >> 8;
    const int rem = g & 255;                               // d*2+s
    float h = 0.f;
    for (int ch = 0; ch < NCHUNK; ch++) {
        const size_t idx = (((size_t)b*NCHUNK + ch) * CDIM * DSTATE) + rem;
        g_hinit[idx] = h;
        h = fmaf(g_aggA[idx], h, g_aggH[idx]);
    }
}

// ---------------------------------------------------------------------------
// K4: scan — pure: loads dt/xi/z, recomputes dA, sequential h update,
// gate, store y. 128 threads (thread = d), tiny smem -> high occupancy.
// ---------------------------------------------------------------------------
__global__ __launch_bounds__(128)
void k_scan(const float* __restrict__ A_log, const float* __restrict__ D_param) {
    __shared__ float bc_s[CHUNK*4];
    const int ch = blockIdx.x;
    const int b  = blockIdx.y;
    const int l0 = ch * CHUNK;
    const int d  = threadIdx.x;

    {
        const float* bcg = g_bc + ((size_t)b * LSEQ + l0) * 4;
        for (int i = d; i < CHUNK*4; i += 128) bc_s[i] = bcg[i];
    }
    const float a0L = -__expf(A_log[2*d+0]) * LOG2E;
    const float a1L = -__expf(A_log[2*d+1]) * LOG2E;
    const float Dp  = D_param[d];
    const size_t base = (((size_t)b*NCHUNK + ch)*CDIM + d)*DSTATE;
    float h0 = g_hinit[base+0];
    float h1 = g_hinit[base+1];

    const size_t off = ((size_t)b * LSEQ + l0) * CDIM + d;
    const float* dtp = g_dt    + off;
    const float* xip = g_xi    + off;
    const float* zp  = g_zsilu + off;
    float*       yp  = g_y     + off;
    __syncthreads();

#pragma unroll 4
    for (int l = 0; l < CHUNK; l++) {
        float dt = dtp[(size_t)l*CDIM];
        float xi = xip[(size_t)l*CDIM];
        float zv = zp [(size_t)l*CDIM];
        float e0 = exp2f(dt * a0L);
        float e1 = exp2f(dt * a1L);
        float dbx = dt * xi;
        h0 = fmaf(e0, h0, dbx * bc_s[l*4+0]);
        h1 = fmaf(e1, h1, dbx * bc_s[l*4+1]);
        float y = fmaf(h0, bc_s[l*4+2], fmaf(h1, bc_s[l*4+3], Dp * xi));
        yp[(size_t)l*CDIM] = y * zv;
    }
}

// ---------------------------------------------------------------------------
// K5: out_proj SGEMM (BM=128 tokens, BN=128=OUTC, BK=16, 8x8 microtile)
// + fused LayerNorm + transposed coalesced writes to out[b][o][l].
// ---------------------------------------------------------------------------
#define SM5_FLOATS (128*132 + 256)

__global__ __launch_bounds__(256, 2)
void k_outproj(const float* __restrict__ Wout, const float* __restrict__ gamma,
               const float* __restrict__ beta, float* __restrict__ out) {
    extern __shared__ float sm5[];
    float* As = sm5;               // [16][132] during mainloop
    float* Bs = sm5 + 16*132;      // [16][132]
    const int b  = blockIdx.y;
    const int m0 = blockIdx.x * 128;
    const int tid = threadIdx.x;
    const int tx = tid & 15, ty = tid >> 4;
    const float* yb = g_y + (size_t)b * LSEQ * CDIM;

    float acc[8][8];
#pragma unroll
    for (int i = 0; i < 8; i++)
#pragma unroll
        for (int j = 0; j < 8; j++) acc[i][j] = 0.f;

    const int lrow = tid >> 2;     // 0..63
    const int lc   = tid & 3;

    for (int k0 = 0; k0 < CDIM; k0 += 16) {
#pragma unroll
        for (int r = 0; r < 2; r++) {
            int m = lrow + r*64;
            float4 v = *reinterpret_cast<const float4*>(
                &yb[(size_t)(m0 + m)*CDIM + k0 + lc*4]);
            As[(lc*4+0)*132 + m] = v.x;
            As[(lc*4+1)*132 + m] = v.y;
            As[(lc*4+2)*132 + m] = v.z;
            As[(lc*4+3)*132 + m] = v.w;
        }
#pragma unroll
        for (int r = 0; r < 2; r++) {
            int n = lrow + r*64;
            float4 w = *reinterpret_cast<const float4*>(
                &Wout[(size_t)n*CDIM + k0 + lc*4]);
            Bs[(lc*4+0)*132 + n] = w.x;
            Bs[(lc*4+1)*132 + n] = w.y;
            Bs[(lc*4+2)*132 + n] = w.z;
            Bs[(lc*4+3)*132 + n] = w.w;
        }
        __syncthreads();
#pragma unroll
        for (int k = 0; k < 16; k++) {
            float a[8], bv[8];
            *reinterpret_cast<float4*>(&a[0]) = *reinterpret_cast<const float4*>(&As[k*132 + ty*8]);
            *reinterpret_cast<float4*>(&a[4]) = *reinterpret_cast<const float4*>(&As[k*132 + ty*8 + 4]);
            *reinterpret_cast<float4*>(&bv[0]) = *reinterpret_cast<const float4*>(&Bs[k*132 + tx*8]);
            *reinterpret_cast<float4*>(&bv[4]) = *reinterpret_cast<const float4*>(&Bs[k*132 + tx*8 + 4]);
#pragma unroll
            for (int i = 0; i < 8; i++)
#pragma unroll
                for (int j = 0; j < 8; j++)
                    acc[i][j] = fmaf(a[i], bv[j], acc[i][j]);
        }
        __syncthreads();
    }

    // ---- epilogue: LN over o for each token, transposed write ----
    float* out_s = sm5;            // [128 o][132 m] (reuses As/Bs space)
    float* mu_s  = sm5 + 128*132;  // [128]
    float* rs_s  = mu_s + 128;     // [128]

#pragma unroll
    for (int j = 0; j < 8; j++)
#pragma unroll
        for (int i = 0; i < 8; i++)
            out_s[(tx*8 + j)*132 + ty*8 + i] = acc[i][j];
    __syncthreads();

    if (tid < 128) {
        float s = 0.f, q = 0.f;
#pragma unroll 8
        for (int o = 0; o < 128; o++) {
            float v = out_s[o*132 + tid];
            s += v;
            q = fmaf(v, v, q);
        }
        float mu = s * (1.0f/128.0f);
        float var = q * (1.0f/128.0f) - mu*mu;
        mu_s[tid] = mu;
        rs_s[tid] = rsqrtf(var + 1e-5f);
    }
    __syncthreads();

    for (int p = tid; p < 128*32; p += 256) {
        int o  = p >> 5;
        int l4 = (p & 31) * 4;
        float g  = gamma[o];
        float bt = beta[o];
        float4 v = *reinterpret_cast<const float4*>(&out_s[o*132 + l4]);
        v.x = fmaf((v.x - mu_s[l4+0]) * rs_s[l4+0], g, bt);
        v.y = fmaf((v.y - mu_s[l4+1]) * rs_s[l4+1], g, bt);
        v.z = fmaf((v.z - mu_s[l4+2]) * rs_s[l4+2], g, bt);
        v.w = fmaf((v.w - mu_s[l4+3]) * rs_s[l4+3], g, bt);
        *reinterpret_cast<float4*>(&out[((size_t)(b*OUTC + o))*LSEQ + m0 + l4]) = v;
    }
}

// ---------------------------------------------------------------------------
extern "C" void kernel_launch(void* const* d_in, const int* in_sizes, int n_in,
                              void* d_out, int out_size) {
    const float* x          = (const float*)d_in[0];
    const float* in_proj_w  = (const float*)d_in[1];
    const float* conv_w     = (const float*)d_in[2];
    const float* conv_b     = (const float*)d_in[3];
    const float* x_proj_w   = (const float*)d_in[4];
    const float* dt_proj_w  = (const float*)d_in[5];
    const float* dt_proj_b  = (const float*)d_in[6];
    const float* A_log      = (const float*)d_in[7];
    const float* D_param    = (const float*)d_in[8];
    const float* out_proj_w = (const float*)d_in[9];
    const float* ln_gamma   = (const float*)d_in[10];
    const float* ln_beta    = (const float*)d_in[11];
    float* out = (float*)d_out;

    const int sm2 = SM2_FLOATS * sizeof(float);   // ~63 KB
    const int sm5 = SM5_FLOATS * sizeof(float);   // ~68.6 KB
    cudaFuncSetAttribute(k_phaseA,  cudaFuncAttributeMaxDynamicSharedMemorySize, sm2);
    cudaFuncSetAttribute(k_outproj, cudaFuncAttributeMaxDynamicSharedMemorySize, sm5);

    k_inproj <<<dim3(LSEQ/128, 2, B_), 256>>>(x, in_proj_w);
    k_phaseA <<<dim3(NCHUNK, B_), 128, sm2>>>(conv_w, conv_b, x_proj_w,
                                              dt_proj_w, dt_proj_b, A_log);
    k_combine<<<16, 256>>>();
    k_scan   <<<dim3(NCHUNK, B_), 128>>>(A_log, D_param);
    k_outproj<<<dim3(LSEQ/128, B_), 256, sm5>>>(out_proj_w, ln_gamma, ln_beta, out);
}